// round 16
// baseline (speedup 1.0000x reference)
#include <cuda_runtime.h>
#include <math.h>

#define BSZ   2
#define NA    2
#define NB    2
#define NPTS  4096
#define DD    1024
#define WD    2048

#define ET_LIM ((size_t)BSZ * NA * NPTS * DD)   // 16,777,216 complex
#define EW_LIM ((size_t)BSZ * NB * NPTS * WD)   // 33,554,432 complex
#define K_LIM  ((size_t)BSZ * NB * NA * WD * DD)
#define G_LIM  ((size_t)BSZ * NB * NA * NPTS * DD) // 33,554,432 (= out_size floats!)
#define PTS_N  (BSZ * NPTS * 3)   // 24576
#define T_N    (NA * 3 * DD)      // 6144
#define W_N    (NB * 3 * WD)      // 12288

// Statics re-tested under provably-safe d_out writes (<= out_size floats).
__device__ float2 g_eW[BSZ * NB * NPTS * WD];   // 268 MB
__device__ float2 g_eT[BSZ * NA * NPTS * DD];   // 134 MB
__device__ float2 g_K [BSZ * NB * NA * WD * DD];// 134 MB
__device__ float  g_Gi[BSZ * NB * NA * NPTS * DD]; // 134 MB (imag staging)

// dtype-agnostic element load: f=1 -> bf16, f=0 -> fp32
__device__ __forceinline__ float ldin(const void* p, int i, int f) {
    if (f) {
        unsigned int v = (unsigned int)((const unsigned short*)p)[i];
        return __uint_as_float(v << 16);
    }
    return ((const float*)p)[i];
}

// per-array dtype probe (reads 256 bytes; in-bounds for every input under
// both dtypes). bf16 data -> even 16-bit words are real values (sane
// exponents ~100%); fp32 data -> they are mantissa low-halves (~11% sane).
__device__ __forceinline__ int probe_bf16(const void* arr) {
    const unsigned short* u = (const unsigned short*)arr;
    int sane = 0;
#pragma unroll
    for (int i = 0; i < 64; i++) {
        unsigned short v = u[2 * i];
        int e = (v >> 7) & 0xFF;
        if (v == 0 || (e >= 107 && e <= 135)) sane++;
    }
    return (sane >= 32) ? 1 : 0;
}

__global__ void fill_zero_kernel(float* out, size_t cnt) {
    size_t i = (size_t)blockIdx.x * blockDim.x + threadIdx.x;
    if (i < cnt) out[i] = 0.0f;
}

// ---------------- stage 1: phase tables (precise sincosf, one-time) ---------
__global__ void phases_T_kernel(const void* __restrict__ pts,
                                const void* __restrict__ T) {
    __shared__ int s_f[2];
    const int tid = threadIdx.x;
    if (tid < 2) s_f[tid] = probe_bf16(tid == 0 ? pts : T);
    __syncthreads();
    const int fp = s_f[0], ft = s_f[1];

    size_t idx = (size_t)blockIdx.x * blockDim.x + tid;
    if (idx >= ET_LIM) return;
    unsigned d  = (unsigned)idx & (DD - 1);
    unsigned n  = ((unsigned)idx >> 10) & (NPTS - 1);
    unsigned a  = ((unsigned)idx >> 22) & (NA - 1);
    unsigned bs = (unsigned)idx >> 23;
    int pb = (bs * NPTS + n) * 3;
    int tb = a * 3 * DD + d;
    float th = ldin(pts, pb + 0, fp) * ldin(T, tb, ft)
             + ldin(pts, pb + 1, fp) * ldin(T, tb + DD, ft)
             + ldin(pts, pb + 2, fp) * ldin(T, tb + 2 * DD, ft);
    float s, c;
    sincosf(th, &s, &c);
    g_eT[idx] = make_float2(c, s);
}

__global__ void phases_W_kernel(const void* __restrict__ pts,
                                const void* __restrict__ W) {
    __shared__ int s_f[2];
    const int tid = threadIdx.x;
    if (tid < 2) s_f[tid] = probe_bf16(tid == 0 ? pts : W);
    __syncthreads();
    const int fp = s_f[0], fw = s_f[1];

    size_t idx = (size_t)blockIdx.x * blockDim.x + tid;
    if (idx >= EW_LIM) return;
    unsigned w  = (unsigned)idx & (WD - 1);
    unsigned n  = ((unsigned)idx >> 11) & (NPTS - 1);
    unsigned b  = ((unsigned)idx >> 23) & (NB - 1);
    unsigned bs = (unsigned)idx >> 24;
    int pb = (bs * NPTS + n) * 3;
    int wb = b * 3 * WD + w;
    float th = ldin(pts, pb + 0, fp) * ldin(W, wb, fw)
             + ldin(pts, pb + 1, fp) * ldin(W, wb + WD, fw)
             + ldin(pts, pb + 2, fp) * ldin(W, wb + 2 * WD, fw);
    float s, c;
    sincosf(th, &s, &c);
    g_eW[idx] = make_float2(c, s);
}

// ---------------- stage 2: K = eW^H @ eT (z = bs*4 + b*2 + a) ----------------
#define BM 64
#define BN 64
#define BK 32

__global__ __launch_bounds__(256) void kmat_kernel() {
    const int z  = blockIdx.z;
    const int bs = z >> 2, bb = (z >> 1) & 1, aa = z & 1;
    const size_t aBase = (size_t)(bs * NB + bb) * NPTS * WD;  // eW [n][w]
    const size_t bBase = (size_t)(bs * NA + aa) * NPTS * DD;  // eT [n][d]
    const size_t kBase = (size_t)z * WD * DD;

    __shared__ float2 sA[BK][BM];
    __shared__ float2 sB[BK][BN];

    const int w0 = blockIdx.y * BM;
    const int d0 = blockIdx.x * BN;
    const int tid = threadIdx.x;
    const int tx = tid & 15, ty = tid >> 4;
    const int m0 = ty * 4, n0 = tx * 4;

    float2 acc[4][4];
#pragma unroll
    for (int i = 0; i < 4; i++)
#pragma unroll
        for (int j = 0; j < 4; j++) acc[i][j] = make_float2(0.f, 0.f);

    const int la = tid & 63, ka = tid >> 6;

    for (int k0 = 0; k0 < NPTS; k0 += BK) {
#pragma unroll
        for (int r = 0; r < 8; r++) {
            int k = ka + r * 4;
            sA[k][la] = g_eW[aBase + (size_t)(k0 + k) * WD + w0 + la];
            sB[k][la] = g_eT[bBase + (size_t)(k0 + k) * DD + d0 + la];
        }
        __syncthreads();
#pragma unroll
        for (int kk = 0; kk < BK; kk++) {
            float2 aw[4], bt[4];
#pragma unroll
            for (int i = 0; i < 4; i++) aw[i] = sA[kk][m0 + i];
#pragma unroll
            for (int j = 0; j < 4; j++) bt[j] = sB[kk][n0 + j];
#pragma unroll
            for (int i = 0; i < 4; i++)
#pragma unroll
                for (int j = 0; j < 4; j++) {
                    acc[i][j].x += aw[i].x * bt[j].x + aw[i].y * bt[j].y;  // conj(eW)*eT
                    acc[i][j].y += aw[i].x * bt[j].y - aw[i].y * bt[j].x;
                }
        }
        __syncthreads();
    }

#pragma unroll
    for (int i = 0; i < 4; i++)
#pragma unroll
        for (int j = 0; j < 4; j++)
            g_K[kBase + (size_t)(w0 + m0 + i) * DD + d0 + n0 + j] = acc[i][j];
}

// ---------------- stage 3: G = eW @ K; re -> d_out (guarded), im -> g_Gi -----
__global__ __launch_bounds__(256) void gmat_kernel(float* __restrict__ outf,
                                                   size_t os_f) {
    const int z  = blockIdx.z;
    const int bs = z >> 2, bb = (z >> 1) & 1;
    const size_t aBase = (size_t)(bs * NB + bb) * NPTS * WD;  // eW [n][w]
    const size_t kBase = (size_t)z * WD * DD;                 // K  [w][d]
    const size_t gBase = (size_t)z * NPTS * DD;

    __shared__ float2 sAt[BM][BK];   // [n][k(w)] natural order, scalar access
    __shared__ float2 sB[BK][BN];    // [k(w)][d]

    const int nblk0 = blockIdx.y * BM;
    const int d0    = blockIdx.x * BN;
    const int tid = threadIdx.x;
    const int tx = tid & 15, ty = tid >> 4;
    const int m0 = ty * 4, n0 = tx * 4;

    float2 acc[4][4];
#pragma unroll
    for (int i = 0; i < 4; i++)
#pragma unroll
        for (int j = 0; j < 4; j++) acc[i][j] = make_float2(0.f, 0.f);

    const int kA = tid & 31, nA = tid >> 5;
    const int dB = tid & 63, kB = tid >> 6;

    for (int k0 = 0; k0 < WD; k0 += BK) {
#pragma unroll
        for (int r = 0; r < 8; r++) {
            int nn = nA + r * 8;
            sAt[nn][kA] = g_eW[aBase + (size_t)(nblk0 + nn) * WD + k0 + kA];
        }
#pragma unroll
        for (int r = 0; r < 8; r++) {
            int k = kB + r * 4;
            sB[k][dB] = g_K[kBase + (size_t)(k0 + k) * DD + d0 + dB];
        }
        __syncthreads();
#pragma unroll
        for (int kk = 0; kk < BK; kk++) {
            float2 aw[4], bk[4];
#pragma unroll
            for (int i = 0; i < 4; i++) aw[i] = sAt[m0 + i][kk];
#pragma unroll
            for (int j = 0; j < 4; j++) bk[j] = sB[kk][n0 + j];
#pragma unroll
            for (int i = 0; i < 4; i++)
#pragma unroll
                for (int j = 0; j < 4; j++) {
                    acc[i][j].x += aw[i].x * bk[j].x - aw[i].y * bk[j].y;
                    acc[i][j].y += aw[i].x * bk[j].y + aw[i].y * bk[j].x;
                }
        }
        __syncthreads();
    }

#pragma unroll
    for (int i = 0; i < 4; i++)
#pragma unroll
        for (int j = 0; j < 4; j++) {
            size_t oi = gBase + (size_t)(nblk0 + m0 + i) * DD + d0 + n0 + j;
            if (oi < os_f) outf[oi] = acc[i][j].x;   // real part into d_out
            g_Gi[oi] = acc[i][j].y;                  // imag into static staging
        }
}

// ---------------- stage 4: row-normalize, rotate by conj(eT), REAL out ------
__global__ __launch_bounds__(256) void norm_kernel(const void* __restrict__ pts,
                                                   const void* __restrict__ T,
                                                   float* __restrict__ outf,
                                                   size_t os_f) {
    __shared__ int s_f[2];
    __shared__ float red[8];
    const int tid = threadIdx.x;
    if (tid < 2) s_f[tid] = probe_bf16(tid == 0 ? pts : T);
    __syncthreads();
    const int fp = s_f[0], ft = s_f[1];

    const int r  = blockIdx.x;          // z*4096 + n
    const int n  = r & (NPTS - 1);
    const int z  = r >> 12;
    const int aa = z & 1;
    const int bs = z >> 2;

    float gr[4], gi[4];
    float ss = 0.f;
#pragma unroll
    for (int j = 0; j < 4; j++) {
        size_t fo = (size_t)r * DD + tid + j * 256;   // < G_LIM by construction
        gr[j] = (fo < os_f) ? outf[fo] : 0.f;
        gi[j] = g_Gi[fo];
        ss += gr[j] * gr[j] + gi[j] * gi[j];
    }
#pragma unroll
    for (int o = 16; o > 0; o >>= 1) ss += __shfl_xor_sync(0xffffffffu, ss, o);
    if ((tid & 31) == 0) red[tid >> 5] = ss;
    __syncthreads();
    float tot = red[0] + red[1] + red[2] + red[3] + red[4] + red[5] + red[6] + red[7];
    const float scale = 32.0f * rsqrtf(fmaxf(tot, 1e-30f));

    int pb = (bs * NPTS + n) * 3;
    const float p0 = ldin(pts, pb + 0, fp);
    const float p1 = ldin(pts, pb + 1, fp);
    const float p2 = ldin(pts, pb + 2, fp);

#pragma unroll
    for (int j = 0; j < 4; j++) {
        int d = tid + j * 256;
        float th = p0 * ldin(T, aa * 3 * DD + d, ft)
                 + p1 * ldin(T, aa * 3 * DD + DD + d, ft)
                 + p2 * ldin(T, aa * 3 * DD + 2 * DD + d, ft);
        float s, c;
        sincosf(th, &s, &c);
        size_t fo = (size_t)r * DD + d;
        if (fo < os_f)
            outf[fo] = (gr[j] * c + gi[j] * s) * scale;  // Re(G * conj(eT)) * scale
    }
}

// ---------------- launch ------------------------------------------------------
static bool find3(const int* s, int n, int va, int vb, int vc,
                  int* ia, int* ib, int* ic) {
    *ia = *ib = *ic = -1;
    for (int i = 0; i < n; i++) {
        if (s[i] == va && *ia < 0) *ia = i;
        else if (s[i] == vb && *ib < 0) *ib = i;
        else if (s[i] == vc && *ic < 0) *ic = i;
    }
    return (*ia >= 0 && *ib >= 0 && *ic >= 0);
}

extern "C" void kernel_launch(void* const* d_in, const int* in_sizes, int n_in,
                              void* d_out, int out_size) {
    if (!d_out) return;
    float* outf = (float*)d_out;

    // d_out = out_size FLOAT32 elements (empirically established R12-R15).
    size_t os_f = (size_t)(out_size > 0 ? out_size : 0);
    if (os_f > G_LIM) os_f = G_LIM;

    const void* pts = nullptr;
    const void* T   = nullptr;
    const void* W   = nullptr;
    int ip, it, iw;
    if (d_in && in_sizes && n_in >= 3 &&
        find3(in_sizes, n_in, PTS_N, T_N, W_N, &ip, &it, &iw)) {
        pts = d_in[ip]; T = d_in[it]; W = d_in[iw];
    }
    if (!pts || !T || !W) {
        if (os_f > 0)
            fill_zero_kernel<<<(int)((os_f + 255) / 256), 256>>>(outf, os_f);
        return;
    }

    phases_T_kernel<<<(int)(ET_LIM / 256), 256>>>(pts, T);
    phases_W_kernel<<<(int)(EW_LIM / 256), 256>>>(pts, W);

    dim3 g2(DD / BN, WD / BM, BSZ * NB * NA);    // (16, 32, 8)
    kmat_kernel<<<g2, 256>>>();

    dim3 g3(DD / BN, NPTS / BM, BSZ * NB * NA);  // (16, 64, 8)
    gmat_kernel<<<g3, 256>>>(outf, os_f);

    norm_kernel<<<BSZ * NB * NA * NPTS, 256>>>(pts, T, outf, os_f);
}

// round 17
// speedup vs baseline: 1.3125x; 1.3125x over previous
#include <cuda_runtime.h>
#include <math.h>

#define BSZ   2
#define NA    2
#define NB    2
#define NPTS  4096
#define DD    1024
#define WD    2048

#define ET_LIM ((size_t)BSZ * NA * NPTS * DD)   // 16,777,216 complex
#define EW_LIM ((size_t)BSZ * NB * NPTS * WD)   // 33,554,432 complex
#define K_LIM  ((size_t)BSZ * NB * NA * WD * DD)
#define G_LIM  ((size_t)BSZ * NB * NA * NPTS * DD) // 33,554,432 (= out_size floats)
#define PTS_N  (BSZ * NPTS * 3)   // 24576
#define T_N    (NA * 3 * DD)      // 6144
#define W_N    (NB * 3 * WD)      // 12288

__device__ float2 g_eW[BSZ * NB * NPTS * WD];      // 268 MB
__device__ float2 g_eT[BSZ * NA * NPTS * DD];      // 134 MB
__device__ float2 g_K [BSZ * NB * NA * WD * DD];   // 134 MB
__device__ float  g_Gi[BSZ * NB * NA * NPTS * DD]; // 134 MB (imag staging)

// ---------- packed f32x2 helpers (SASS FFMA2; PTX-only path) -----------------
__device__ __forceinline__ void fma2(unsigned long long& d,
                                     unsigned long long a, unsigned long long b) {
    asm("fma.rn.f32x2 %0, %1, %2, %0;" : "+l"(d) : "l"(a), "l"(b));
}
__device__ __forceinline__ unsigned long long pk(float lo, float hi) {
    unsigned long long r;
    asm("mov.b64 %0, {%1, %2};" : "=l"(r) : "f"(lo), "f"(hi));
    return r;
}
__device__ __forceinline__ float2 up(unsigned long long v) {
    float2 r;
    asm("mov.b64 {%0, %1}, %2;" : "=f"(r.x), "=f"(r.y) : "l"(v));
    return r;
}

// dtype-agnostic element load: f=1 -> bf16, f=0 -> fp32
__device__ __forceinline__ float ldin(const void* p, int i, int f) {
    if (f) {
        unsigned int v = (unsigned int)((const unsigned short*)p)[i];
        return __uint_as_float(v << 16);
    }
    return ((const float*)p)[i];
}

__device__ __forceinline__ int probe_bf16(const void* arr) {
    const unsigned short* u = (const unsigned short*)arr;
    int sane = 0;
#pragma unroll
    for (int i = 0; i < 64; i++) {
        unsigned short v = u[2 * i];
        int e = (v >> 7) & 0xFF;
        if (v == 0 || (e >= 107 && e <= 135)) sane++;
    }
    return (sane >= 32) ? 1 : 0;
}

__global__ void fill_zero_kernel(float* out, size_t cnt) {
    size_t i = (size_t)blockIdx.x * blockDim.x + threadIdx.x;
    if (i < cnt) out[i] = 0.0f;
}

// ---------------- stage 1: phase tables --------------------------------------
__global__ void phases_T_kernel(const void* __restrict__ pts,
                                const void* __restrict__ T) {
    __shared__ int s_f[2];
    const int tid = threadIdx.x;
    if (tid < 2) s_f[tid] = probe_bf16(tid == 0 ? pts : T);
    __syncthreads();
    const int fp = s_f[0], ft = s_f[1];

    size_t idx = (size_t)blockIdx.x * blockDim.x + tid;
    if (idx >= ET_LIM) return;
    unsigned d  = (unsigned)idx & (DD - 1);
    unsigned n  = ((unsigned)idx >> 10) & (NPTS - 1);
    unsigned a  = ((unsigned)idx >> 22) & (NA - 1);
    unsigned bs = (unsigned)idx >> 23;
    int pb = (bs * NPTS + n) * 3;
    int tb = a * 3 * DD + d;
    float th = ldin(pts, pb + 0, fp) * ldin(T, tb, ft)
             + ldin(pts, pb + 1, fp) * ldin(T, tb + DD, ft)
             + ldin(pts, pb + 2, fp) * ldin(T, tb + 2 * DD, ft);
    float s, c;
    sincosf(th, &s, &c);
    g_eT[idx] = make_float2(c, s);
}

__global__ void phases_W_kernel(const void* __restrict__ pts,
                                const void* __restrict__ W) {
    __shared__ int s_f[2];
    const int tid = threadIdx.x;
    if (tid < 2) s_f[tid] = probe_bf16(tid == 0 ? pts : W);
    __syncthreads();
    const int fp = s_f[0], fw = s_f[1];

    size_t idx = (size_t)blockIdx.x * blockDim.x + tid;
    if (idx >= EW_LIM) return;
    unsigned w  = (unsigned)idx & (WD - 1);
    unsigned n  = ((unsigned)idx >> 11) & (NPTS - 1);
    unsigned b  = ((unsigned)idx >> 23) & (NB - 1);
    unsigned bs = (unsigned)idx >> 24;
    int pb = (bs * NPTS + n) * 3;
    int wb = b * 3 * WD + w;
    float th = ldin(pts, pb + 0, fp) * ldin(W, wb, fw)
             + ldin(pts, pb + 1, fp) * ldin(W, wb + WD, fw)
             + ldin(pts, pb + 2, fp) * ldin(W, wb + 2 * WD, fw);
    float s, c;
    sincosf(th, &s, &c);
    g_eW[idx] = make_float2(c, s);
}

// ---------------- stage 2: K = eW^H @ eT (FFMA2 dual-accumulator) ------------
#define BM 64
#define BN 64
#define BK 32

__global__ __launch_bounds__(256, 2) void kmat_kernel() {
    const int z  = blockIdx.z;
    const int bs = z >> 2, bb = (z >> 1) & 1, aa = z & 1;
    const size_t aBase = (size_t)(bs * NB + bb) * NPTS * WD;  // eW [n][w]
    const size_t bBase = (size_t)(bs * NA + aa) * NPTS * DD;  // eT [n][d]
    const size_t kBase = (size_t)z * WD * DD;

    __shared__ float2 sA[BK][BM];
    __shared__ float2 sB[BK][BN];

    const int w0 = blockIdx.y * BM;
    const int d0 = blockIdx.x * BN;
    const int tid = threadIdx.x;
    const int tx = tid & 15, ty = tid >> 4;
    const int m0 = ty * 4, n0 = tx * 4;

    unsigned long long acc1[4][4], acc2[4][4];
#pragma unroll
    for (int i = 0; i < 4; i++)
#pragma unroll
        for (int j = 0; j < 4; j++) { acc1[i][j] = 0ull; acc2[i][j] = 0ull; }

    const int la = tid & 63, ka = tid >> 6;

    for (int k0 = 0; k0 < NPTS; k0 += BK) {
#pragma unroll
        for (int r = 0; r < 8; r++) {
            int k = ka + r * 4;
            sA[k][la] = g_eW[aBase + (size_t)(k0 + k) * WD + w0 + la];
            sB[k][la] = g_eT[bBase + (size_t)(k0 + k) * DD + d0 + la];
        }
        __syncthreads();
#pragma unroll
        for (int kk = 0; kk < BK; kk++) {
            unsigned long long bt[4];
#pragma unroll
            for (int j = 0; j < 4; j++)
                bt[j] = *(const unsigned long long*)&sB[kk][n0 + j];
#pragma unroll
            for (int i = 0; i < 4; i++) {
                float2 aw = sA[kk][m0 + i];
                unsigned long long ax = pk(aw.x, aw.x);
                unsigned long long ay = pk(aw.y, aw.y);
#pragma unroll
                for (int j = 0; j < 4; j++) {
                    fma2(acc1[i][j], ax, bt[j]);
                    fma2(acc2[i][j], ay, bt[j]);
                }
            }
        }
        __syncthreads();
    }

#pragma unroll
    for (int i = 0; i < 4; i++)
#pragma unroll
        for (int j = 0; j < 4; j++) {
            float2 a1 = up(acc1[i][j]), a2 = up(acc2[i][j]);
            // conj(eW)*eT: re = Σ ax*bx + ay*by ; im = Σ ax*by − ay*bx
            float2 v = make_float2(a1.x + a2.y, a1.y - a2.x);
            g_K[kBase + (size_t)(w0 + m0 + i) * DD + d0 + n0 + j] = v;
        }
}

// ---------------- stage 3: G = eW @ K (FFMA2); re -> d_out, im -> g_Gi -------
__global__ __launch_bounds__(256, 2) void gmat_kernel(float* __restrict__ outf,
                                                      size_t os_f) {
    const int z  = blockIdx.z;
    const int bs = z >> 2, bb = (z >> 1) & 1;
    const size_t aBase = (size_t)(bs * NB + bb) * NPTS * WD;  // eW [n][w]
    const size_t kBase = (size_t)z * WD * DD;                 // K  [w][d]
    const size_t gBase = (size_t)z * NPTS * DD;

    __shared__ float2 sAt[BM][BK];   // [n][k(w)]
    __shared__ float2 sB[BK][BN];    // [k(w)][d]

    const int nblk0 = blockIdx.y * BM;
    const int d0    = blockIdx.x * BN;
    const int tid = threadIdx.x;
    const int tx = tid & 15, ty = tid >> 4;
    const int m0 = ty * 4, n0 = tx * 4;

    unsigned long long acc1[4][4], acc2[4][4];
#pragma unroll
    for (int i = 0; i < 4; i++)
#pragma unroll
        for (int j = 0; j < 4; j++) { acc1[i][j] = 0ull; acc2[i][j] = 0ull; }

    const int kA = tid & 31, nA = tid >> 5;
    const int dB = tid & 63, kB = tid >> 6;

    for (int k0 = 0; k0 < WD; k0 += BK) {
#pragma unroll
        for (int r = 0; r < 8; r++) {
            int nn = nA + r * 8;
            sAt[nn][kA] = g_eW[aBase + (size_t)(nblk0 + nn) * WD + k0 + kA];
        }
#pragma unroll
        for (int r = 0; r < 8; r++) {
            int k = kB + r * 4;
            sB[k][dB] = g_K[kBase + (size_t)(k0 + k) * DD + d0 + dB];
        }
        __syncthreads();
#pragma unroll
        for (int kk = 0; kk < BK; kk++) {
            unsigned long long bk[4];
#pragma unroll
            for (int j = 0; j < 4; j++)
                bk[j] = *(const unsigned long long*)&sB[kk][n0 + j];
#pragma unroll
            for (int i = 0; i < 4; i++) {
                float2 aw = sAt[m0 + i][kk];
                unsigned long long ax = pk(aw.x, aw.x);
                unsigned long long ay = pk(aw.y, aw.y);
#pragma unroll
                for (int j = 0; j < 4; j++) {
                    fma2(acc1[i][j], ax, bk[j]);
                    fma2(acc2[i][j], ay, bk[j]);
                }
            }
        }
        __syncthreads();
    }

#pragma unroll
    for (int i = 0; i < 4; i++)
#pragma unroll
        for (int j = 0; j < 4; j++) {
            float2 a1 = up(acc1[i][j]), a2 = up(acc2[i][j]);
            // eW*K: re = Σ ax*bx − ay*by ; im = Σ ax*by + ay*bx
            size_t oi = gBase + (size_t)(nblk0 + m0 + i) * DD + d0 + n0 + j;
            if (oi < os_f) outf[oi] = a1.x - a2.y;
            g_Gi[oi] = a1.y + a2.x;
        }
}

// ---------------- stage 4: row-normalize, rotate by conj(eT), REAL out ------
__global__ __launch_bounds__(256) void norm_kernel(const void* __restrict__ pts,
                                                   const void* __restrict__ T,
                                                   float* __restrict__ outf,
                                                   size_t os_f) {
    __shared__ int s_f[2];
    __shared__ float red[8];
    const int tid = threadIdx.x;
    if (tid < 2) s_f[tid] = probe_bf16(tid == 0 ? pts : T);
    __syncthreads();
    const int fp = s_f[0], ft = s_f[1];

    const int r  = blockIdx.x;          // z*4096 + n
    const int n  = r & (NPTS - 1);
    const int z  = r >> 12;
    const int aa = z & 1;
    const int bs = z >> 2;

    float gr[4], gi[4];
    float ss = 0.f;
#pragma unroll
    for (int j = 0; j < 4; j++) {
        size_t fo = (size_t)r * DD + tid + j * 256;
        gr[j] = (fo < os_f) ? outf[fo] : 0.f;
        gi[j] = g_Gi[fo];
        ss += gr[j] * gr[j] + gi[j] * gi[j];
    }
#pragma unroll
    for (int o = 16; o > 0; o >>= 1) ss += __shfl_xor_sync(0xffffffffu, ss, o);
    if ((tid & 31) == 0) red[tid >> 5] = ss;
    __syncthreads();
    float tot = red[0] + red[1] + red[2] + red[3] + red[4] + red[5] + red[6] + red[7];
    const float scale = 32.0f * rsqrtf(fmaxf(tot, 1e-30f));

    int pb = (bs * NPTS + n) * 3;
    const float p0 = ldin(pts, pb + 0, fp);
    const float p1 = ldin(pts, pb + 1, fp);
    const float p2 = ldin(pts, pb + 2, fp);

#pragma unroll
    for (int j = 0; j < 4; j++) {
        int d = tid + j * 256;
        float th = p0 * ldin(T, aa * 3 * DD + d, ft)
                 + p1 * ldin(T, aa * 3 * DD + DD + d, ft)
                 + p2 * ldin(T, aa * 3 * DD + 2 * DD + d, ft);
        float s, c;
        sincosf(th, &s, &c);
        size_t fo = (size_t)r * DD + d;
        if (fo < os_f)
            outf[fo] = (gr[j] * c + gi[j] * s) * scale;  // Re(G*conj(eT))*scale
    }
}

// ---------------- launch ------------------------------------------------------
static bool find3(const int* s, int n, int va, int vb, int vc,
                  int* ia, int* ib, int* ic) {
    *ia = *ib = *ic = -1;
    for (int i = 0; i < n; i++) {
        if (s[i] == va && *ia < 0) *ia = i;
        else if (s[i] == vb && *ib < 0) *ib = i;
        else if (s[i] == vc && *ic < 0) *ic = i;
    }
    return (*ia >= 0 && *ib >= 0 && *ic >= 0);
}

extern "C" void kernel_launch(void* const* d_in, const int* in_sizes, int n_in,
                              void* d_out, int out_size) {
    if (!d_out) return;
    float* outf = (float*)d_out;

    size_t os_f = (size_t)(out_size > 0 ? out_size : 0);   // float32 elements
    if (os_f > G_LIM) os_f = G_LIM;

    const void* pts = nullptr;
    const void* T   = nullptr;
    const void* W   = nullptr;
    int ip, it, iw;
    if (d_in && in_sizes && n_in >= 3 &&
        find3(in_sizes, n_in, PTS_N, T_N, W_N, &ip, &it, &iw)) {
        pts = d_in[ip]; T = d_in[it]; W = d_in[iw];
    }
    if (!pts || !T || !W) {
        if (os_f > 0)
            fill_zero_kernel<<<(int)((os_f + 255) / 256), 256>>>(outf, os_f);
        return;
    }

    phases_T_kernel<<<(int)(ET_LIM / 256), 256>>>(pts, T);
    phases_W_kernel<<<(int)(EW_LIM / 256), 256>>>(pts, W);

    dim3 g2(DD / BN, WD / BM, BSZ * NB * NA);    // (16, 32, 8)
    kmat_kernel<<<g2, 256>>>();

    dim3 g3(DD / BN, NPTS / BM, BSZ * NB * NA);  // (16, 64, 8)
    gmat_kernel<<<g3, 256>>>(outf, os_f);

    norm_kernel<<<BSZ * NB * NA * NPTS, 256>>>(pts, T, outf, os_f);
}